// round 1
// baseline (speedup 1.0000x reference)
#include <cuda_runtime.h>
#include <cstdint>

typedef unsigned long long ull;

#define MULQ 16
#define NPAIR 136
// packed-weight layout offsets (in floats) inside g_W / sW
#define OFF_W0    0        // 136*16  = 2176   out0 <- y      (A000 * sym w000)
#define OFF_W110  2176     // 136*16  = 2176   out0 <- dot    (A110 * sym w110)
#define OFF_W112  4352     // 136*80  = 10880  out2 <- t[5]   (A112*C112 coeffs * sym w112), flat (w*5+k)
#define OFF_W101  15232    // 16*16*16= 4096   out1           (A101 * w101), layout [u][v][w]
#define W_TOTAL   19328

#define NT 256
#define XSTRIDE 257
#define SMEM_BYTES ((W_TOTAL + 64 * XSTRIDE) * 4)

__device__ __align__(16) float g_W[W_TOTAL];

// ---------------- f32x2 helpers (sm_103a packed fp32) ----------------
__device__ __forceinline__ ull pack2(float a, float b) {
    ull r;
    asm("mov.b64 %0, {%1, %2};" : "=l"(r) : "f"(a), "f"(b));
    return r;
}
__device__ __forceinline__ void fma2(ull& acc, ull a, ull b) {
    asm("fma.rn.f32x2 %0, %1, %2, %0;" : "+l"(acc) : "l"(a), "l"(b));
}
__device__ __forceinline__ float2 unpack2(ull v) {
    float2 r;
    asm("mov.b64 {%0, %1}, %2;" : "=f"(r.x), "=f"(r.y) : "l"(v));
    return r;
}

// decode packed symmetric pair index p -> (u, v) with u <= v
__device__ __forceinline__ void decode_pair(int p, int& u, int& v) {
    int uu = 0, r = p;
    while (r >= MULQ - uu) { r -= MULQ - uu; ++uu; }
    u = uu;
    v = uu + r;
}

// ---------------- weight prep: symmetrize + fold all constants ----------------
// A000 = sqrt(1/512), A110 = A000/sqrt(3), A101 = 1/16, A112 = sqrt(5/256)
// t_k raw combos used by main kernel: r0=m01+m10, r1=m02+m20, r2=m12+m21,
// r3=m00-m11, r4=2*m22-(m00+m11).
// C112 coeffs: k<4 -> (1/sqrt2)/sqrt5, k=4 -> 1/(sqrt6*sqrt5).
// Folded scales: A112/sqrt(10) == A000, A112/sqrt(30) == A110 (exact identities).
__global__ void prep_kernel(const float* __restrict__ w000, const float* __restrict__ w101,
                            const float* __restrict__ w110, const float* __restrict__ w112) {
    const float A000  = 0.044194173824159216f;
    const float A110  = 0.025515518153991442f;
    const float A101  = 0.0625f;
    const float S112A = 0.044194173824159216f;  // A112/sqrt(10)
    const float S112B = 0.025515518153991442f;  // A112/sqrt(30)

    const int tid = blockIdx.x * blockDim.x + threadIdx.x;
    const int nth = gridDim.x * blockDim.x;

    for (int idx = tid; idx < NPAIR * MULQ; idx += nth) {
        int p = idx >> 4, w = idx & 15;
        int u, v;
        decode_pair(p, u, v);
        float c0 = w000[u * 256 + v * 16 + w];
        float c1 = w110[u * 256 + v * 16 + w];
        if (u != v) {
            c0 += w000[v * 256 + u * 16 + w];
            c1 += w110[v * 256 + u * 16 + w];
        }
        g_W[OFF_W0 + idx]   = c0 * A000;
        g_W[OFF_W110 + idx] = c1 * A110;
    }
    for (int idx = tid; idx < NPAIR * 80; idx += nth) {
        int p = idx / 80, f = idx - p * 80;
        int w = f / 5, k = f - 5 * w;
        int u, v;
        decode_pair(p, u, v);
        float c = w112[u * 256 + v * 16 + w];
        if (u != v) c += w112[v * 256 + u * 16 + w];
        g_W[OFF_W112 + idx] = c * (k == 4 ? S112B : S112A);
    }
    for (int idx = tid; idx < 4096; idx += nth) {
        g_W[OFF_W101 + idx] = w101[idx] * A101;
    }
}

// ---------------- main kernel: 1 node / thread, f32x2-packed accumulators ----------------
__global__ void __launch_bounds__(NT)
tsq_kernel(const float* __restrict__ nf, const float* __restrict__ nm,
           float* __restrict__ out, int nnodes) {
    extern __shared__ float smem[];
    float* sW = smem;
    float* sX = smem + W_TOTAL;
    const int t = threadIdx.x;

    // stage packed weights (broadcast-read later, conflict free)
    {
        const float4* src = (const float4*)g_W;
        float4* dst = (float4*)sW;
#pragma unroll 4
        for (int i = t; i < W_TOTAL / 4; i += NT) dst[i] = src[i];
    }
    // stage x = feats + messages, transposed: sX[f*XSTRIDE + node_local]
    {
        const int base4 = blockIdx.x * (NT * 16);
        const int limit4 = nnodes * 16;
        const float4* a4 = (const float4*)nf;
        const float4* b4 = (const float4*)nm;
        for (int i = t; i < NT * 16; i += NT) {
            int gi = base4 + i;
            float4 a = make_float4(0.f, 0.f, 0.f, 0.f), b = a;
            if (gi < limit4) { a = a4[gi]; b = b4[gi]; }
            int nl = i >> 4, fq = (i & 15) << 2;
            sX[(fq + 0) * XSTRIDE + nl] = a.x + b.x;
            sX[(fq + 1) * XSTRIDE + nl] = a.y + b.y;
            sX[(fq + 2) * XSTRIDE + nl] = a.z + b.z;
            sX[(fq + 3) * XSTRIDE + nl] = a.w + b.w;
        }
    }
    __syncthreads();

    const ull* sW0   = (const ull*)(sW + OFF_W0);
    const ull* sW110 = (const ull*)(sW + OFF_W110);
    const ull* sW112 = (const ull*)(sW + OFF_W112);
    const ull* sW101 = (const ull*)(sW + OFF_W101);

    ull acc0[8];
    ull acc2[40];
#pragma unroll
    for (int j = 0; j < 8; j++) acc0[j] = 0ull;
#pragma unroll
    for (int j = 0; j < 40; j++) acc2[j] = 0ull;

    // ---- out0 (16) + out2 (16x5) over 136 symmetric pairs ----
    int p = 0;
#pragma unroll 1
    for (int u = 0; u < MULQ; ++u) {
        float a0 = sX[u * XSTRIDE + t];
        float ax = sX[(MULQ + 3 * u + 0) * XSTRIDE + t];
        float ay = sX[(MULQ + 3 * u + 1) * XSTRIDE + t];
        float az = sX[(MULQ + 3 * u + 2) * XSTRIDE + t];
#pragma unroll 1
        for (int v = u; v < MULQ; ++v, ++p) {
            float b0 = sX[v * XSTRIDE + t];
            float bx = sX[(MULQ + 3 * v + 0) * XSTRIDE + t];
            float by = sX[(MULQ + 3 * v + 1) * XSTRIDE + t];
            float bz = sX[(MULQ + 3 * v + 2) * XSTRIDE + t];

            float y   = a0 * b0;
            float m00 = ax * bx, m01 = ax * by, m02 = ax * bz;
            float m10 = ay * bx, m11 = ay * by, m12 = ay * bz;
            float m20 = az * bx, m21 = az * by, m22 = az * bz;
            float h  = m00 + m11;
            float s  = h + m22;
            float r0 = m01 + m10, r1 = m02 + m20, r2 = m12 + m21;
            float r3 = m00 - m11;
            float r4 = fmaf(2.f, m22, -h);

            ull yd  = pack2(y, y);
            ull sd  = pack2(s, s);
            ull t01 = pack2(r0, r1), t23 = pack2(r2, r3), t40 = pack2(r4, r0);
            ull t12 = pack2(r1, r2), t34 = pack2(r3, r4);

            const ull* w0p = sW0 + p * 8;
            const ull* w1p = sW110 + p * 8;
#pragma unroll
            for (int j = 0; j < 8; j++) {
                fma2(acc0[j], w0p[j], yd);
                fma2(acc0[j], w1p[j], sd);
            }
            const ull* w2p = sW112 + p * 40;
#pragma unroll
            for (int j = 0; j < 40; j += 5) {
                fma2(acc2[j + 0], w2p[j + 0], t01);
                fma2(acc2[j + 1], w2p[j + 1], t23);
                fma2(acc2[j + 2], w2p[j + 2], t40);
                fma2(acc2[j + 3], w2p[j + 3], t12);
                fma2(acc2[j + 4], w2p[j + 4], t34);
            }
        }
    }

    // ---- out1 (16x3): out1[w,k] = sum_u x1[u,k] * (sum_v W101[u,v,w] x0[v]) ----
    ull acc1[24];
#pragma unroll
    for (int j = 0; j < 24; j++) acc1[j] = 0ull;
#pragma unroll 1
    for (int u = 0; u < MULQ; ++u) {
        ull G[8];
#pragma unroll
        for (int j = 0; j < 8; j++) G[j] = 0ull;
        const ull* wq = sW101 + u * 128;
#pragma unroll 1
        for (int v = 0; v < MULQ; ++v) {
            float x0v = sX[v * XSTRIDE + t];
            ull xd = pack2(x0v, x0v);
#pragma unroll
            for (int j = 0; j < 8; j++) fma2(G[j], wq[v * 8 + j], xd);
        }
        float k0 = sX[(MULQ + 3 * u + 0) * XSTRIDE + t];
        float k1 = sX[(MULQ + 3 * u + 1) * XSTRIDE + t];
        float k2 = sX[(MULQ + 3 * u + 2) * XSTRIDE + t];
        ull k0d = pack2(k0, k0), k1d = pack2(k1, k1), k2d = pack2(k2, k2);
#pragma unroll
        for (int j = 0; j < 8; j++) {
            fma2(acc1[j], G[j], k0d);
            fma2(acc1[8 + j], G[j], k1d);
            fma2(acc1[16 + j], G[j], k2d);
        }
    }

    // ---- epilogue: concat [out0(16) | out1(48, w*3+k) | out2(80, w*5+k)] ----
    const int node = blockIdx.x * NT + t;
    if (node < nnodes) {
        float o[144];
#pragma unroll
        for (int j = 0; j < 8; j++) {
            float2 v = unpack2(acc0[j]);
            o[2 * j] = v.x;
            o[2 * j + 1] = v.y;
        }
#pragma unroll
        for (int k = 0; k < 3; k++)
#pragma unroll
            for (int j = 0; j < 8; j++) {
                float2 v = unpack2(acc1[k * 8 + j]);
                o[16 + (2 * j) * 3 + k] = v.x;
                o[16 + (2 * j + 1) * 3 + k] = v.y;
            }
#pragma unroll
        for (int j = 0; j < 40; j++) {
            float2 v = unpack2(acc2[j]);
            o[64 + 2 * j] = v.x;
            o[64 + 2 * j + 1] = v.y;
        }
        float4* o4 = (float4*)(out + (size_t)node * 144);
#pragma unroll
        for (int i = 0; i < 36; i++)
            o4[i] = make_float4(o[4 * i], o[4 * i + 1], o[4 * i + 2], o[4 * i + 3]);
    }
}

extern "C" void kernel_launch(void* const* d_in, const int* in_sizes, int n_in,
                              void* d_out, int out_size) {
    const float* nf   = (const float*)d_in[0];
    const float* nm   = (const float*)d_in[1];
    const float* w000 = (const float*)d_in[2];
    const float* w101 = (const float*)d_in[3];
    const float* w110 = (const float*)d_in[4];
    const float* w112 = (const float*)d_in[5];
    const int nnodes = in_sizes[0] / 64;

    prep_kernel<<<32, 256>>>(w000, w101, w110, w112);

    cudaFuncSetAttribute(tsq_kernel, cudaFuncAttributeMaxDynamicSharedMemorySize, SMEM_BYTES);
    const int grid = (nnodes + NT - 1) / NT;
    tsq_kernel<<<grid, NT, SMEM_BYTES>>>(nf, nm, (float*)d_out, nnodes);
}

// round 3
// speedup vs baseline: 1.0247x; 1.0247x over previous
#include <cuda_runtime.h>
#include <cstdint>

typedef unsigned long long ull;

#define MULQ 16
#define NPAIR 136
// packed-weight layout offsets (floats) inside g_W / sW
#define OFF_WA    0        // 136*2*16 = 4352 : per (p,half): 4x float4 {w0[2j],w0[2j+1],w110[2j],w110[2j+1]}
#define OFF_W112  4352     // 136*2*40 = 10880: per (p,half): 40 floats (wl*5+k), coeff-folded sym w112
#define OFF_W101  15232    // 16*2*16*8 = 4096: per (u,half,v): 8 floats (A101*w101)
#define W_TOTAL   19328

#define NT 512
#define NODES_PER_CTA 256
#define XSTRIDE 257
#define SMEM_BYTES ((W_TOTAL + 64 * XSTRIDE) * 4)

__device__ __align__(16) float g_W[W_TOTAL];

// ---------------- f32x2 helpers ----------------
__device__ __forceinline__ ull pack2(float a, float b) {
    ull r;
    asm("mov.b64 %0, {%1, %2};" : "=l"(r) : "f"(a), "f"(b));
    return r;
}
__device__ __forceinline__ void fma2(ull& acc, ull a, ull b) {
    asm("fma.rn.f32x2 %0, %1, %2, %0;" : "+l"(acc) : "l"(a), "l"(b));
}
__device__ __forceinline__ float2 unpack2(ull v) {
    float2 r;
    asm("mov.b64 {%0, %1}, %2;" : "=f"(r.x), "=f"(r.y) : "l"(v));
    return r;
}

__device__ __forceinline__ void decode_pair(int p, int& u, int& v) {
    int uu = 0, r = p;
    while (r >= MULQ - uu) { r -= MULQ - uu; ++uu; }
    u = uu;
    v = uu + r;
}

// ---------------- weight prep: symmetrize + fold constants + half-split layout ----------------
__global__ void prep_kernel(const float* __restrict__ w000, const float* __restrict__ w101,
                            const float* __restrict__ w110, const float* __restrict__ w112) {
    const float A000  = 0.044194173824159216f;
    const float A110  = 0.025515518153991442f;
    const float A101  = 0.0625f;
    const float S112A = 0.044194173824159216f;  // A112/sqrt(10)
    const float S112B = 0.025515518153991442f;  // A112/sqrt(30)

    const int tid = blockIdx.x * blockDim.x + threadIdx.x;
    const int nth = gridDim.x * blockDim.x;

    // WA: interleaved w000/w110 pairs per (p, half)
    for (int idx = tid; idx < NPAIR * 32; idx += nth) {
        int p = idx >> 5, r = idx & 31;
        int half = r >> 4, q = r & 15;
        int j = q >> 2, pos = q & 3;
        int wl = 2 * j + (pos & 1);
        int w = half * 8 + wl;
        int u, v;
        decode_pair(p, u, v);
        const float* src = (pos >= 2) ? w110 : w000;
        float c = src[u * 256 + v * 16 + w];
        if (u != v) c += src[v * 256 + u * 16 + w];
        g_W[OFF_WA + idx] = c * ((pos >= 2) ? A110 : A000);
    }
    // W112: per (p, half): 40 floats flat (wl*5 + k)
    for (int idx = tid; idx < NPAIR * 80; idx += nth) {
        int p = idx / 80, r = idx - p * 80;
        int half = r / 40, f = r - half * 40;
        int wl = f / 5, k = f - 5 * wl;
        int w = half * 8 + wl;
        int u, v;
        decode_pair(p, u, v);
        float c = w112[u * 256 + v * 16 + w];
        if (u != v) c += w112[v * 256 + u * 16 + w];
        g_W[OFF_W112 + idx] = c * (k == 4 ? S112B : S112A);
    }
    // W101: per (u, half, v): 8 floats
    for (int idx = tid; idx < 4096; idx += nth) {
        int u = idx >> 8, r = idx & 255;
        int half = r >> 7, v = (r >> 3) & 15, j = r & 7;
        int w = half * 8 + j;
        g_W[OFF_W101 + idx] = w101[u * 256 + v * 16 + w] * A101;
    }
}

// ---------------- main kernel: 512 thr, 256 nodes/CTA, w-half split, f32x2 w-pair lanes ----------------
__global__ void __launch_bounds__(NT)
tsq_kernel(const float* __restrict__ nf, const float* __restrict__ nm,
           float* __restrict__ out, int nnodes) {
    extern __shared__ float smem[];
    float* sW = smem;
    float* sX = smem + W_TOTAL;
    const int t = threadIdx.x;

    // stage weights
    {
        const float4* src = (const float4*)g_W;
        float4* dst = (float4*)sW;
        for (int i = t; i < W_TOTAL / 4; i += NT) dst[i] = src[i];
    }
    // stage x = feats + messages, transposed: sX[comp*XSTRIDE + node_local]
    {
        const int base4 = blockIdx.x * (NODES_PER_CTA * 16);
        const int limit4 = nnodes * 16;
        const float4* a4 = (const float4*)nf;
        const float4* b4 = (const float4*)nm;
        for (int i = t; i < NODES_PER_CTA * 16; i += NT) {
            int gi = base4 + i;
            float4 a = make_float4(0.f, 0.f, 0.f, 0.f), b = a;
            if (gi < limit4) { a = a4[gi]; b = b4[gi]; }
            int nl = i >> 4, fq = (i & 15) << 2;
            sX[(fq + 0) * XSTRIDE + nl] = a.x + b.x;
            sX[(fq + 1) * XSTRIDE + nl] = a.y + b.y;
            sX[(fq + 2) * XSTRIDE + nl] = a.z + b.z;
            sX[(fq + 3) * XSTRIDE + nl] = a.w + b.w;
        }
    }
    __syncthreads();

    const int nl = t & (NODES_PER_CTA - 1);
    const int wh = t >> 8;  // w-half: 0 -> w 0..7, 1 -> w 8..15

    // ulonglong2 = 16 bytes = 4 floats.
    // WA: per (p,half) 16 floats = 4 u2; per p 8 u2.
    // W2: per (p,half) 40 floats = 10 u2; per p 20 u2.
    // WQ: per (u,half) 128 floats = 32 u2; per u 64 u2; per v 2 u2.
    const ulonglong2* WA = (const ulonglong2*)sW + wh * 4;                    // + p*8
    const ulonglong2* W2 = (const ulonglong2*)(sW + OFF_W112) + wh * 10;      // + p*20
    const ulonglong2* WQ = (const ulonglong2*)(sW + OFF_W101) + wh * 32;      // + u*64 + 2v

    ull acc0[4], acc2[20];
#pragma unroll
    for (int j = 0; j < 4; j++) acc0[j] = 0ull;
#pragma unroll
    for (int j = 0; j < 20; j++) acc2[j] = 0ull;

    // ---- out0 (8 w) + out2 (8 w x 5 k) over 136 symmetric pairs ----
    int p = 0;
#pragma unroll 1
    for (int u = 0; u < MULQ; ++u) {
        const float a0 = sX[u * XSTRIDE + nl];
        const float ax = sX[(MULQ + 3 * u + 0) * XSTRIDE + nl];
        const float ay = sX[(MULQ + 3 * u + 1) * XSTRIDE + nl];
        const float az = sX[(MULQ + 3 * u + 2) * XSTRIDE + nl];
#pragma unroll 1
        for (int v = u; v < MULQ; ++v, ++p) {
            const float b0 = sX[v * XSTRIDE + nl];
            const float bx = sX[(MULQ + 3 * v + 0) * XSTRIDE + nl];
            const float by = sX[(MULQ + 3 * v + 1) * XSTRIDE + nl];
            const float bz = sX[(MULQ + 3 * v + 2) * XSTRIDE + nl];

            float y   = a0 * b0;
            float m00 = ax * bx, m01 = ax * by, m02 = ax * bz;
            float m10 = ay * bx, m11 = ay * by, m12 = ay * bz;
            float m20 = az * bx, m21 = az * by, m22 = az * bz;
            float h  = m00 + m11;
            float s  = h + m22;
            float r0 = m01 + m10, r1 = m02 + m20, r2 = m12 + m21;
            float r3 = m00 - m11;
            float r4 = fmaf(2.f, m22, -h);

            ull yd  = pack2(y, y);
            ull sd  = pack2(s, s);
            ull t01 = pack2(r0, r1), t23 = pack2(r2, r3), t40 = pack2(r4, r0);
            ull t12 = pack2(r1, r2), t34 = pack2(r3, r4);

            const ulonglong2* wa = WA + p * 8;
            {
                ulonglong2 q0 = wa[0], q1 = wa[1], q2 = wa[2], q3 = wa[3];
                fma2(acc0[0], q0.x, yd); fma2(acc0[0], q0.y, sd);
                fma2(acc0[1], q1.x, yd); fma2(acc0[1], q1.y, sd);
                fma2(acc0[2], q2.x, yd); fma2(acc0[2], q2.y, sd);
                fma2(acc0[3], q3.x, yd); fma2(acc0[3], q3.y, sd);
            }
            const ulonglong2* w2 = W2 + p * 20;
            {
                ulonglong2 q;
                q = w2[0]; fma2(acc2[0],  q.x, t01); fma2(acc2[1],  q.y, t23);
                q = w2[1]; fma2(acc2[2],  q.x, t40); fma2(acc2[3],  q.y, t12);
                q = w2[2]; fma2(acc2[4],  q.x, t34); fma2(acc2[5],  q.y, t01);
                q = w2[3]; fma2(acc2[6],  q.x, t23); fma2(acc2[7],  q.y, t40);
                q = w2[4]; fma2(acc2[8],  q.x, t12); fma2(acc2[9],  q.y, t34);
                q = w2[5]; fma2(acc2[10], q.x, t01); fma2(acc2[11], q.y, t23);
                q = w2[6]; fma2(acc2[12], q.x, t40); fma2(acc2[13], q.y, t12);
                q = w2[7]; fma2(acc2[14], q.x, t34); fma2(acc2[15], q.y, t01);
                q = w2[8]; fma2(acc2[16], q.x, t23); fma2(acc2[17], q.y, t40);
                q = w2[9]; fma2(acc2[18], q.x, t12); fma2(acc2[19], q.y, t34);
            }
        }
    }

    // ---- out1 (8 w x 3 k): out1[w,k] = sum_u x1[u,k] * (sum_v W101[u,v,w] x0[v]) ----
    ull acc1[12];
#pragma unroll
    for (int j = 0; j < 12; j++) acc1[j] = 0ull;
#pragma unroll 1
    for (int u = 0; u < MULQ; ++u) {
        ull G0 = 0, G1 = 0, G2 = 0, G3 = 0;
        const ulonglong2* wq = WQ + u * 64;
#pragma unroll 4
        for (int v = 0; v < MULQ; ++v) {
            float x0v = sX[v * XSTRIDE + nl];
            ull xd = pack2(x0v, x0v);
            ulonglong2 q0 = wq[2 * v], q1 = wq[2 * v + 1];
            fma2(G0, q0.x, xd); fma2(G1, q0.y, xd);
            fma2(G2, q1.x, xd); fma2(G3, q1.y, xd);
        }
        float k0 = sX[(MULQ + 3 * u + 0) * XSTRIDE + nl];
        float k1 = sX[(MULQ + 3 * u + 1) * XSTRIDE + nl];
        float k2 = sX[(MULQ + 3 * u + 2) * XSTRIDE + nl];
        ull k0d = pack2(k0, k0), k1d = pack2(k1, k1), k2d = pack2(k2, k2);
        fma2(acc1[0], G0, k0d); fma2(acc1[1], G1, k0d); fma2(acc1[2],  G2, k0d); fma2(acc1[3],  G3, k0d);
        fma2(acc1[4], G0, k1d); fma2(acc1[5], G1, k1d); fma2(acc1[6],  G2, k1d); fma2(acc1[7],  G3, k1d);
        fma2(acc1[8], G0, k2d); fma2(acc1[9], G1, k2d); fma2(acc1[10], G2, k2d); fma2(acc1[11], G3, k2d);
    }

    // ---- epilogue: this thread owns w in [wh*8, wh*8+8) of all three irreps ----
    const int node = blockIdx.x * NODES_PER_CTA + nl;
    if (node < nnodes) {
        float* dst = out + (size_t)node * 144;

        // out0: global floats [wh*8, wh*8+8)
        {
            float o[8];
#pragma unroll
            for (int j = 0; j < 4; j++) {
                float2 v = unpack2(acc0[j]);
                o[2 * j] = v.x;
                o[2 * j + 1] = v.y;
            }
            float4* p0 = (float4*)(dst + wh * 8);
            p0[0] = make_float4(o[0], o[1], o[2], o[3]);
            p0[1] = make_float4(o[4], o[5], o[6], o[7]);
        }
        // out1: global floats [16 + wh*24, 16 + wh*24 + 24), layout (w*3 + k)
        {
            float o[24];
#pragma unroll
            for (int k = 0; k < 3; k++)
#pragma unroll
                for (int j = 0; j < 4; j++) {
                    float2 v = unpack2(acc1[k * 4 + j]);
                    o[(2 * j) * 3 + k] = v.x;
                    o[(2 * j + 1) * 3 + k] = v.y;
                }
            float4* p1 = (float4*)(dst + 16 + wh * 24);
#pragma unroll
            for (int i = 0; i < 6; i++)
                p1[i] = make_float4(o[4 * i], o[4 * i + 1], o[4 * i + 2], o[4 * i + 3]);
        }
        // out2: global floats [64 + wh*40, 64 + wh*40 + 40), layout (w*5 + k)
        {
            float o[40];
#pragma unroll
            for (int m = 0; m < 20; m++) {
                float2 v = unpack2(acc2[m]);
                o[2 * m] = v.x;
                o[2 * m + 1] = v.y;
            }
            float4* p2 = (float4*)(dst + 64 + wh * 40);
#pragma unroll
            for (int i = 0; i < 10; i++)
                p2[i] = make_float4(o[4 * i], o[4 * i + 1], o[4 * i + 2], o[4 * i + 3]);
        }
    }
}

extern "C" void kernel_launch(void* const* d_in, const int* in_sizes, int n_in,
                              void* d_out, int out_size) {
    const float* nf   = (const float*)d_in[0];
    const float* nm   = (const float*)d_in[1];
    const float* w000 = (const float*)d_in[2];
    const float* w101 = (const float*)d_in[3];
    const float* w110 = (const float*)d_in[4];
    const float* w112 = (const float*)d_in[5];
    const int nnodes = in_sizes[0] / 64;

    prep_kernel<<<32, 256>>>(w000, w101, w110, w112);

    cudaFuncSetAttribute(tsq_kernel, cudaFuncAttributeMaxDynamicSharedMemorySize, SMEM_BYTES);
    const int grid = (nnodes + NODES_PER_CTA - 1) / NODES_PER_CTA;
    tsq_kernel<<<grid, NT, SMEM_BYTES>>>(nf, nm, (float*)d_out, nnodes);
}